// round 16
// baseline (speedup 1.0000x reference)
#include <cuda_runtime.h>
#include <cuda_bf16.h>
#include <cuda_fp16.h>
#include <cstdint>

// Problem constants
#define BATCH   2
#define SEQ     2048
#define DMODEL  1024
#define NHEADS  16
#define DK      64
#define BH      (BATCH * NHEADS)          // 32
#define MTOT    (BATCH * SEQ)             // 4096

// Scratch (declared as float arrays; used as fp16 payloads):
// g_X (fp16, uint4 units): [m_blk(256)][k_blk(64)][lane(32)] -> 4 uint32 (A-fragments)
// g_W (fp16, uint2 units) per matrix: [kb(64)][n(1024)][t(4)] (B-fragments)
// g_Q, g_K (fp16, 32 uint32 per row s): pair layout idx32 = kb*8 + 2*(j&3) + (j>>2)
// g_V (fp16): idx(s,d) = ((s>>4)*64+d)*16 + p*2 + (s&1), k2=(s&15)>>1, p=2*(k2&3)+(k2>>2)
__device__ float g_X[(size_t)MTOT * DMODEL];
__device__ float g_W[(size_t)3 * DMODEL * DMODEL];
__device__ float g_Q[(size_t)BH * SEQ * DK];
__device__ float g_K[(size_t)BH * SEQ * DK];
__device__ float g_V[(size_t)BH * SEQ * DK];

// ---------------------------------------------------------------------------
// Helpers
// ---------------------------------------------------------------------------
__device__ __forceinline__ float ex2f(float x) {
    float r;
    asm("ex2.approx.f32 %0, %1;" : "=f"(r) : "f"(x));
    return r;
}

__device__ __forceinline__ uint32_t pack_f16x2(float lo, float hi) {
    uint32_t r;
    asm("cvt.rn.f16x2.f32 %0, %1, %2;" : "=r"(r) : "f"(hi), "f"(lo));
    return r;
}

__device__ __forceinline__ void mma_f16(float c[4], const uint32_t a[4],
                                        uint32_t b0, uint32_t b1) {
    asm volatile(
        "mma.sync.aligned.m16n8k16.row.col.f32.f16.f16.f32 "
        "{%0,%1,%2,%3}, {%4,%5,%6,%7}, {%8,%9}, {%0,%1,%2,%3};"
        : "+f"(c[0]), "+f"(c[1]), "+f"(c[2]), "+f"(c[3])
        : "r"(a[0]), "r"(a[1]), "r"(a[2]), "r"(a[3]), "r"(b0), "r"(b1));
}

__device__ __forceinline__ void cp16(void* s, const void* gp) {
    uint32_t sa = (uint32_t)__cvta_generic_to_shared(s);
    asm volatile("cp.async.cg.shared.global [%0], [%1], 16;" :: "r"(sa), "l"(gp));
}
__device__ __forceinline__ void cp_commit() {
    asm volatile("cp.async.commit_group;");
}
__device__ __forceinline__ void cp_wait_all() {
    asm volatile("cp.async.wait_group 0;");
}

// ---------------------------------------------------------------------------
// Kernel 0a: X -> fp16 fragment-quad layout
// ---------------------------------------------------------------------------
__global__ void perm_x(const float* __restrict__ X)
{
    int i = blockIdx.x * blockDim.x + threadIdx.x;    // 524288 total
    int lane = i & 31;
    int t = lane & 3, g = lane >> 2;
    int kb = (i >> 5) & 63;
    int mb = i >> 11;
    const float* s = X + (size_t)(mb * 16) * DMODEL + kb * 16;
    uint32_t a0 = pack_f16x2(s[(size_t)g * DMODEL + 2*t],       s[(size_t)g * DMODEL + 2*t + 1]);
    uint32_t a1 = pack_f16x2(s[(size_t)(g+8) * DMODEL + 2*t],   s[(size_t)(g+8) * DMODEL + 2*t + 1]);
    uint32_t a2 = pack_f16x2(s[(size_t)g * DMODEL + 2*t + 8],   s[(size_t)g * DMODEL + 2*t + 9]);
    uint32_t a3 = pack_f16x2(s[(size_t)(g+8) * DMODEL + 2*t+8], s[(size_t)(g+8) * DMODEL + 2*t + 9]);
    reinterpret_cast<uint4*>(g_X)[i] = make_uint4(a0, a1, a2, a3);
}

// Kernel 0b: W -> fp16 k-pair layout; blockIdx.y selects matrix
__global__ void perm_w(const float* __restrict__ w0,
                       const float* __restrict__ w1,
                       const float* __restrict__ w2)
{
    const float* src = (blockIdx.y == 0) ? w0 : (blockIdx.y == 1) ? w1 : w2;
    uint2* dst = reinterpret_cast<uint2*>(g_W) + (size_t)blockIdx.y * 262144;
    int i = blockIdx.x * blockDim.x + threadIdx.x;    // 262144 total
    int t = i & 3;
    int n = (i >> 2) & 1023;
    int kb = i >> 12;
    uint32_t r0 = pack_f16x2(src[(size_t)(kb*16 + 2*t)     * DMODEL + n],
                             src[(size_t)(kb*16 + 2*t + 1) * DMODEL + n]);
    uint32_t r1 = pack_f16x2(src[(size_t)(kb*16 + 2*t + 8) * DMODEL + n],
                             src[(size_t)(kb*16 + 2*t + 9) * DMODEL + n]);
    dst[i] = make_uint2(r0, r1);
}

// ---------------------------------------------------------------------------
// Kernel 1: QKV projection, fp16 m16n8k16, fp32 accum.
// BM=128, BN=128, BK=32 (2 k16 steps). 8 warps as 2x4, warp tile 64x32.
// acc = 64 regs -> 2 CTAs/SM. cp.async double buffer.
// ---------------------------------------------------------------------------
#define BM 128
#define BN 128
#define GEMM_SMEM_BYTES (2 * 8192 + 2 * 8192)    // 32768
#define NKTILES 32
#define QSCALE  0.18033688011112042f   // 0.125 * log2(e)

__global__ __launch_bounds__(256, 2)
void qkv_gemm_kernel(const float* __restrict__ bq,
                     const float* __restrict__ bk,
                     const float* __restrict__ bv)
{
    extern __shared__ uint32_t sg[];
    uint4* As = reinterpret_cast<uint4*>(sg);            // 2 x 512 uint4
    uint2* Bs = reinterpret_cast<uint2*>(sg + 2 * 2048); // 2 x 1024 uint2

    const uint2* Wp = reinterpret_cast<const uint2*>(g_W) + (size_t)blockIdx.z * 262144;
    const float* bias = (blockIdx.z == 0) ? bq : (blockIdx.z == 1) ? bk : bv;

    const int m0 = blockIdx.y * BM;
    const int n0 = blockIdx.x * BN;
    const int tid  = threadIdx.x;
    const int lane = tid & 31;
    const int warp = tid >> 5;
    const int g = lane >> 2;
    const int t = lane & 3;
    const int wm = warp >> 2;     // 0..1 -> rows 64*wm
    const int wn = warp & 3;      // 0..3 -> cols 32*wn
    const int m0b = m0 >> 4;

    auto load_ktile = [&](int kt, int buf) {
        uint4* Ab = As + buf * 512;
        uint2* Bb = Bs + buf * 1024;
        const int kb0 = kt * 2;
        #pragma unroll
        for (int it = 0; it < 2; it++) {
            int idx = tid + it * 256;
            int lc = idx & 31, kb = (idx >> 5) & 1, mb = idx >> 6;   // mb 0..7
            const uint4* src = reinterpret_cast<const uint4*>(g_X) +
                ((size_t)(m0b + mb) * 64 + kb0 + kb) * 32 + lc;
            cp16(&Ab[(mb * 2 + kb) * 32 + lc], src);
        }
        #pragma unroll
        for (int it = 0; it < 2; it++) {
            int idx = tid + it * 256;
            int kb = idx >> 8, rem = idx & 255;
            int nl = rem >> 1, t2 = (rem & 1) * 2;
            const uint2* src = Wp + ((size_t)(kb0 + kb) * 1024 + n0 + nl) * 4 + t2;
            cp16(&Bb[(kb * 128 + nl) * 4 + t2], src);
        }
        cp_commit();
    };

    load_ktile(0, 0);

    float acc[4][4][4];
    #pragma unroll
    for (int fm = 0; fm < 4; fm++)
        #pragma unroll
        for (int fn = 0; fn < 4; fn++)
            #pragma unroll
            for (int e = 0; e < 4; e++) acc[fm][fn][e] = 0.0f;

    for (int kt = 0; kt < NKTILES; kt++) {
        const int buf = kt & 1;
        cp_wait_all();
        __syncthreads();

        if (kt + 1 < NKTILES) load_ktile(kt + 1, buf ^ 1);

        const uint4* Ab = As + buf * 512;
        const uint2* Bb = Bs + buf * 1024;

        #pragma unroll
        for (int ks = 0; ks < 2; ks++) {
            uint32_t a[4][4];
            #pragma unroll
            for (int fm = 0; fm < 4; fm++) {
                uint4 av = Ab[((wm * 4 + fm) * 2 + ks) * 32 + lane];
                a[fm][0] = av.x; a[fm][1] = av.y; a[fm][2] = av.z; a[fm][3] = av.w;
            }
            #pragma unroll
            for (int fn = 0; fn < 4; fn++) {
                uint2 bp = Bb[(ks * 128 + wn * 32 + fn * 8 + g) * 4 + t];
                #pragma unroll
                for (int fm = 0; fm < 4; fm++) mma_f16(acc[fm][fn], a[fm], bp.x, bp.y);
            }
        }
        __syncthreads();
    }

    const int b  = m0 / SEQ;
    const int s0 = m0 % SEQ;
    const int h0 = n0 >> 6;

    if (blockIdx.z == 2) {
        // V fp16 pair-interleaved
        __half* gV = reinterpret_cast<__half*>(g_V);
        #pragma unroll
        for (int fm = 0; fm < 4; fm++) {
            int r0 = wm * 64 + fm * 16 + g;
            #pragma unroll
            for (int fn = 0; fn < 4; fn++) {
                int c = wn * 32 + fn * 8 + 2 * t;
                int h = h0 + (c >> 6);
                int cc = c & 63;
                float bv0 = bias[n0 + c];
                float bv1 = bias[n0 + c + 1];
                __half* base = gV + (size_t)(b * NHEADS + h) * SEQ * DK;
                int sA = s0 + r0;
                int sB = sA + 8;
                int k2A = (sA & 15) >> 1, pA = 2 * (k2A & 3) + (k2A >> 2);
                int k2B = (sB & 15) >> 1, pB = 2 * (k2B & 3) + (k2B >> 2);
                size_t gA = ((size_t)(sA >> 4) * 64) * 16 + pA * 2 + (sA & 1);
                size_t gB = ((size_t)(sB >> 4) * 64) * 16 + pB * 2 + (sB & 1);
                base[gA + (size_t)cc * 16]       = __float2half(acc[fm][fn][0] + bv0);
                base[gA + (size_t)(cc + 1) * 16] = __float2half(acc[fm][fn][1] + bv1);
                base[gB + (size_t)cc * 16]       = __float2half(acc[fm][fn][2] + bv0);
                base[gB + (size_t)(cc + 1) * 16] = __float2half(acc[fm][fn][3] + bv1);
            }
        }
    } else {
        // Q (scaled) or K: fp16 pair rows, one uint32 per (row, pair)
        uint32_t* Out = reinterpret_cast<uint32_t*>(blockIdx.z == 0 ? g_Q : g_K);
        const float scale = (blockIdx.z == 0) ? QSCALE : 1.0f;
        #pragma unroll
        for (int fm = 0; fm < 4; fm++) {
            int r0 = wm * 64 + fm * 16 + g;
            #pragma unroll
            for (int fn = 0; fn < 4; fn++) {
                int c = wn * 32 + fn * 8 + 2 * t;
                int h = h0 + (c >> 6);
                int cc = c & 63;
                int j = (cc >> 1) & 7;
                int idx32 = (cc >> 4) * 8 + 2 * (j & 3) + (j >> 2);
                float bv0 = bias[n0 + c];
                float bv1 = bias[n0 + c + 1];
                uint32_t* ob = Out + ((size_t)(b * NHEADS + h) * SEQ + s0) * 32;
                ob[(size_t)(r0)     * 32 + idx32] =
                    pack_f16x2((acc[fm][fn][0] + bv0) * scale, (acc[fm][fn][1] + bv1) * scale);
                ob[(size_t)(r0 + 8) * 32 + idx32] =
                    pack_f16x2((acc[fm][fn][2] + bv0) * scale, (acc[fm][fn][3] + bv1) * scale);
            }
        }
    }
}

// ---------------------------------------------------------------------------
// Kernel 2: flash attention, fp16 MMA. QT=128, 4 warps x 32 rows,
// 128-thread CTA, __launch_bounds__(128,3) -> 3 CTAs/SM (12 warps).
// ---------------------------------------------------------------------------
#define QT   128
#define KSTR32 36                     // uint32 stride per K/Q row (144B)
#define NKT  (SEQ / 64)
#define ATTN_SMEM_BYTES (2 * 64 * KSTR32 * 4 + 2 * 2048 * 4)   // 34816

__global__ __launch_bounds__(128, 3)
void attn_kernel(float* __restrict__ out)
{
    extern __shared__ uint32_t smu[];
    uint32_t* Ks = smu;                     // 2 bufs x 64 x KSTR32
    uint32_t* Vs = smu + 2 * 64 * KSTR32;   // 2 bufs x 2048

    const int bh = blockIdx.y;
    const int b  = bh >> 4;
    const int h  = bh & 15;
    const int q0 = blockIdx.x * QT;

    const uint32_t* Qp = reinterpret_cast<const uint32_t*>(g_Q) + ((size_t)bh * SEQ + q0) * 32;
    const uint32_t* Kp = reinterpret_cast<const uint32_t*>(g_K) + (size_t)bh * SEQ * 32;
    const char*     Vp = reinterpret_cast<const char*>(g_V) + (size_t)bh * SEQ * DK * 2;

    const int tid  = threadIdx.x;
    const int lane = tid & 31;
    const int warp = tid >> 5;              // 0..3 -> q rows warp*32
    const int g = lane >> 2;
    const int t = lane & 3;
    const int row0 = warp * 32;

    // Stage 128 Q rows (32 uint32 each) into smem (stride KSTR32, over K area)
    #pragma unroll
    for (int it = 0; it < 8; it++) {
        int idx = tid + it * 128;           // 1024 x 16B
        int r = idx >> 3, ch = idx & 7;
        *reinterpret_cast<uint4*>(&smu[r * KSTR32 + ch * 4]) =
            *reinterpret_cast<const uint4*>(Qp + (size_t)r * 32 + ch * 4);
    }
    __syncthreads();

    uint32_t qfA[4][4], qfB[4][4];
    #pragma unroll
    for (int ks = 0; ks < 4; ks++) {
        uint2 u0 = *reinterpret_cast<const uint2*>(&smu[(row0 + g)      * KSTR32 + ks * 8 + 2 * t]);
        uint2 u1 = *reinterpret_cast<const uint2*>(&smu[(row0 + g + 8)  * KSTR32 + ks * 8 + 2 * t]);
        qfA[ks][0] = u0.x; qfA[ks][1] = u1.x; qfA[ks][2] = u0.y; qfA[ks][3] = u1.y;
        uint2 v0 = *reinterpret_cast<const uint2*>(&smu[(row0 + g + 16) * KSTR32 + ks * 8 + 2 * t]);
        uint2 v1 = *reinterpret_cast<const uint2*>(&smu[(row0 + g + 24) * KSTR32 + ks * 8 + 2 * t]);
        qfB[ks][0] = v0.x; qfB[ks][1] = v1.x; qfB[ks][2] = v0.y; qfB[ks][3] = v1.y;
    }
    __syncthreads();

    // Tile loader: K 8KB (512 x 16B), V 8KB (512 x 16B); 128 threads
    auto load_tile = [&](int kt, int buf) {
        uint32_t* Kb = Ks + buf * 64 * KSTR32;
        uint32_t* Vb = Vs + buf * 2048;
        const uint32_t* kp = Kp + (size_t)kt * 64 * 32;
        const char* vp = Vp + (size_t)kt * 8192;
        #pragma unroll
        for (int it = 0; it < 4; it++) {
            int idx = tid + it * 128;
            int r = idx >> 3, ch = idx & 7;
            cp16(&Kb[r * KSTR32 + ch * 4], kp + (size_t)r * 32 + ch * 4);
        }
        #pragma unroll
        for (int it = 0; it < 4; it++) {
            int idx = tid + it * 128;
            cp16(&Vb[idx * 4], vp + (size_t)idx * 16);
        }
        cp_commit();
    };

    load_tile(0, 0);

    float oaccA[8][4], oaccB[8][4];
    #pragma unroll
    for (int jn = 0; jn < 8; jn++)
        #pragma unroll
        for (int e = 0; e < 4; e++) { oaccA[jn][e] = 0.0f; oaccB[jn][e] = 0.0f; }
    float rsA0 = 0.0f, rsA1 = 0.0f, rsB0 = 0.0f, rsB1 = 0.0f;

    for (int kt = 0; kt < NKT; kt++) {
        const int buf = kt & 1;
        cp_wait_all();
        __syncthreads();

        if (kt + 1 < NKT) load_tile(kt + 1, buf ^ 1);

        const uint32_t* Kb = Ks + buf * 64 * KSTR32;
        const uint32_t* Vb = Vs + buf * 2048;

        #pragma unroll
        for (int j2 = 0; j2 < 4; j2++) {
            float sEA[4] = {0.f,0.f,0.f,0.f}, sEB[4] = {0.f,0.f,0.f,0.f};
            float sOA[4] = {0.f,0.f,0.f,0.f}, sOB[4] = {0.f,0.f,0.f,0.f};
            #pragma unroll
            for (int ks = 0; ks < 4; ks++) {
                int keyE = j2 * 16 + g;
                uint2 kE = *reinterpret_cast<const uint2*>(&Kb[keyE * KSTR32 + ks * 8 + 2 * t]);
                uint2 kO = *reinterpret_cast<const uint2*>(&Kb[(keyE + 8) * KSTR32 + ks * 8 + 2 * t]);
                mma_f16(sEA, qfA[ks], kE.x, kE.y);
                mma_f16(sEB, qfB[ks], kE.x, kE.y);
                mma_f16(sOA, qfA[ks], kO.x, kO.y);
                mma_f16(sOB, qfB[ks], kO.x, kO.y);
            }

            // exp2 (log2 domain), rowsums, pack to fp16 A-fragments
            uint32_t aA[4], aB[4];
            {
                float e0 = ex2f(sEA[0]), e1 = ex2f(sEA[1]);
                float e2 = ex2f(sEA[2]), e3 = ex2f(sEA[3]);
                float o0 = ex2f(sOA[0]), o1 = ex2f(sOA[1]);
                float o2 = ex2f(sOA[2]), o3 = ex2f(sOA[3]);
                rsA0 += e0 + e1 + o0 + o1;
                rsA1 += e2 + e3 + o2 + o3;
                aA[0] = pack_f16x2(e0, e1);
                aA[1] = pack_f16x2(e2, e3);
                aA[2] = pack_f16x2(o0, o1);
                aA[3] = pack_f16x2(o2, o3);
            }
            {
                float e0 = ex2f(sEB[0]), e1 = ex2f(sEB[1]);
                float e2 = ex2f(sEB[2]), e3 = ex2f(sEB[3]);
                float o0 = ex2f(sOB[0]), o1 = ex2f(sOB[1]);
                float o2 = ex2f(sOB[2]), o3 = ex2f(sOB[3]);
                rsB0 += e0 + e1 + o0 + o1;
                rsB1 += e2 + e3 + o2 + o3;
                aB[0] = pack_f16x2(e0, e1);
                aB[1] = pack_f16x2(e2, e3);
                aB[2] = pack_f16x2(o0, o1);
                aB[3] = pack_f16x2(o2, o3);
            }

            // PV: V pair-interleaved (LDS.64)
            #pragma unroll
            for (int jn = 0; jn < 8; jn++) {
                int dcol = jn * 8 + g;
                uint2 bv = *reinterpret_cast<const uint2*>(&Vb[(j2 * 64 + dcol) * 8 + 2 * t]);
                mma_f16(oaccA[jn], aA, bv.x, bv.y);
                mma_f16(oaccB[jn], aB, bv.x, bv.y);
            }
        }
    }

    rsA0 += __shfl_xor_sync(0xffffffffu, rsA0, 1);
    rsA0 += __shfl_xor_sync(0xffffffffu, rsA0, 2);
    rsA1 += __shfl_xor_sync(0xffffffffu, rsA1, 1);
    rsA1 += __shfl_xor_sync(0xffffffffu, rsA1, 2);
    rsB0 += __shfl_xor_sync(0xffffffffu, rsB0, 1);
    rsB0 += __shfl_xor_sync(0xffffffffu, rsB0, 2);
    rsB1 += __shfl_xor_sync(0xffffffffu, rsB1, 1);
    rsB1 += __shfl_xor_sync(0xffffffffu, rsB1, 2);
    float invA0 = 1.0f / (rsA0 + 1e-8f);
    float invA1 = 1.0f / (rsA1 + 1e-8f);
    float invB0 = 1.0f / (rsB0 + 1e-8f);
    float invB1 = 1.0f / (rsB1 + 1e-8f);

    #pragma unroll
    for (int jn = 0; jn < 8; jn++) {
        int dcol = jn * 8 + 2 * t;
        float* base = out + ((size_t)(b * SEQ + q0 + row0 + g)) * DMODEL + h * DK + dcol;
        *reinterpret_cast<float2*>(base) =
            make_float2(oaccA[jn][0] * invA0, oaccA[jn][1] * invA0);
        *reinterpret_cast<float2*>(base + (size_t)8 * DMODEL) =
            make_float2(oaccA[jn][2] * invA1, oaccA[jn][3] * invA1);
        *reinterpret_cast<float2*>(base + (size_t)16 * DMODEL) =
            make_float2(oaccB[jn][0] * invB0, oaccB[jn][1] * invB0);
        *reinterpret_cast<float2*>(base + (size_t)24 * DMODEL) =
            make_float2(oaccB[jn][2] * invB1, oaccB[jn][3] * invB1);
    }
}

// ---------------------------------------------------------------------------
extern "C" void kernel_launch(void* const* d_in, const int* in_sizes, int n_in,
                              void* d_out, int out_size)
{
    const float* x  = (const float*)d_in[0];
    const float* Wq = (const float*)d_in[1];
    const float* bq = (const float*)d_in[2];
    const float* Wk = (const float*)d_in[3];
    const float* bk = (const float*)d_in[4];
    const float* Wv = (const float*)d_in[5];
    const float* bv = (const float*)d_in[6];
    float* out = (float*)d_out;

    cudaFuncSetAttribute(attn_kernel, cudaFuncAttributeMaxDynamicSharedMemorySize,
                         (int)ATTN_SMEM_BYTES);
    cudaFuncSetAttribute(qkv_gemm_kernel, cudaFuncAttributeMaxDynamicSharedMemorySize,
                         (int)GEMM_SMEM_BYTES);

    perm_x<<<524288 / 256, 256>>>(x);
    dim3 wgrid(262144 / 256, 3);
    perm_w<<<wgrid, 256>>>(Wq, Wk, Wv);

    dim3 gemm_grid(DMODEL / BN, MTOT / BM, 3);   // 8 x 32 x 3
    qkv_gemm_kernel<<<gemm_grid, 256, GEMM_SMEM_BYTES>>>(bq, bk, bv);

    dim3 attn_grid(SEQ / QT, BH);                // 16 x 32
    attn_kernel<<<attn_grid, 128, ATTN_SMEM_BYTES>>>(out);
}